// round 13
// baseline (speedup 1.0000x reference)
#include <cuda_runtime.h>
#include <cuda_bf16.h>
#include <math.h>
#include <stdint.h>

#define B_ 4
#define L_ 1024
#define D_ 1024
#define H_ 16
#define DH_ 64
#define M_ (B_*L_)

// ---------------- scratch ----------------
__device__ __nv_bfloat16 g_Xh[M_*D_];
__device__ __nv_bfloat16 g_Xl[M_*D_];
__device__ __nv_bfloat16 g_Wh[3*D_*D_];
__device__ __nv_bfloat16 g_Wl[3*D_*D_];
// Q/K/V bf16 hi/lo splits in [b][h][l][dh] layout (Q pre-scaled by SCL)
__device__ __nv_bfloat16 g_Qh[B_*H_*L_*DH_];
__device__ __nv_bfloat16 g_Ql[B_*H_*L_*DH_];
__device__ __nv_bfloat16 g_Kh[B_*H_*L_*DH_];
__device__ __nv_bfloat16 g_Kl[B_*H_*L_*DH_];
__device__ __nv_bfloat16 g_Vh[B_*H_*L_*DH_];
__device__ __nv_bfloat16 g_Vl[B_*H_*L_*DH_];

// ---------------- helpers ----------------
__device__ __forceinline__ uint32_t smem_u32(const void* p) {
    uint32_t a;
    asm("{ .reg .u64 t; cvta.to.shared.u64 t, %1; cvt.u32.u64 %0, t; }" : "=r"(a) : "l"(p));
    return a;
}
__device__ __forceinline__ float ex2(float x) {
    float y; asm("ex2.approx.ftz.f32 %0, %1;" : "=f"(y) : "f"(x)); return y;
}
__device__ __forceinline__ uint32_t pk2bf(float lo, float hi) {
    uint32_t r;
    asm("cvt.rn.bf16x2.f32 %0, %1, %2;" : "=r"(r) : "f"(hi), "f"(lo));
    return r;
}

#define CP_ASYNC16(dst, src) \
    asm volatile("cp.async.cg.shared.global [%0], [%1], 16;" :: "r"(dst), "l"(src) : "memory")
#define CP_COMMIT() asm volatile("cp.async.commit_group;" ::: "memory")
#define CP_WAIT0()  asm volatile("cp.async.wait_group 0;" ::: "memory")

__device__ __forceinline__ void ldsm_x4(uint32_t* r, uint32_t addr) {
    asm volatile("ldmatrix.sync.aligned.m8n8.x4.shared.b16 {%0,%1,%2,%3}, [%4];"
        : "=r"(r[0]), "=r"(r[1]), "=r"(r[2]), "=r"(r[3]) : "r"(addr));
}
__device__ __forceinline__ void ldsm_x4_t(uint32_t* r, uint32_t addr) {
    asm volatile("ldmatrix.sync.aligned.m8n8.x4.trans.shared.b16 {%0,%1,%2,%3}, [%4];"
        : "=r"(r[0]), "=r"(r[1]), "=r"(r[2]), "=r"(r[3]) : "r"(addr));
}
__device__ __forceinline__ void mma_bf16(float* c, const uint32_t* a, const uint32_t* b) {
    asm volatile("mma.sync.aligned.m16n8k16.row.col.f32.bf16.bf16.f32 "
        "{%0,%1,%2,%3}, {%4,%5,%6,%7}, {%8,%9}, {%0,%1,%2,%3};"
        : "+f"(c[0]), "+f"(c[1]), "+f"(c[2]), "+f"(c[3])
        : "r"(a[0]), "r"(a[1]), "r"(a[2]), "r"(a[3]), "r"(b[0]), "r"(b[1]));
}
__device__ __forceinline__ uint32_t swz(uint32_t bo) { return bo ^ ((bo >> 3) & 0x70); }

// ---------------------------------------------------------------------------
// Merged split fp32 -> bf16 (hi, lo) for X, Wq, Wk, Wv in ONE launch.
// ---------------------------------------------------------------------------
#define NX4 (M_*D_/4)
#define NW4 (D_*D_/4)

__global__ __launch_bounds__(256) void cvt_all(
    const float4* __restrict__ X,  const float4* __restrict__ Wq,
    const float4* __restrict__ Wk, const float4* __restrict__ Wv)
{
    int i = blockIdx.x * 256 + threadIdx.x;
    const float4* src; __nv_bfloat16* dh; __nv_bfloat16* dl; int off;
    if (i < NX4) { src = X; off = i; dh = g_Xh; dl = g_Xl; }
    else {
        int wI = i - NX4;
        int s  = wI / NW4;          // 0,1,2
        off = wI - s * NW4;
        src = (s == 0) ? Wq : (s == 1 ? Wk : Wv);
        dh = g_Wh + (size_t)s * (D_*D_);
        dl = g_Wl + (size_t)s * (D_*D_);
    }
    float4 v = src[off];
    float f[4] = {v.x, v.y, v.z, v.w};
    union { __nv_bfloat16 b[4]; uint2 u; } Hh, Ll;
    #pragma unroll
    for (int j = 0; j < 4; j++) {
        __nv_bfloat16 hb = __float2bfloat16(f[j]);
        Hh.b[j] = hb;
        Ll.b[j] = __float2bfloat16(f[j] - __bfloat162float(hb));
    }
    *(uint2*)(dh + (size_t)off * 4) = Hh.u;
    *(uint2*)(dl + (size_t)off * 4) = Ll.u;
}

// ---------------------------------------------------------------------------
// QKV GEMM via mma.sync bf16 (3-term): CTA 256x128, BK=64, 16 warps (4x4),
// 2-stage single-sync cp.async pipeline. (unchanged from R12)
// ---------------------------------------------------------------------------
#define T_AH 0
#define T_AL 32768
#define T_BH 65536
#define T_BL 81920
#define G_STAGE 98304
#define GSMEM (2*G_STAGE)
#define SCL_F 0.18033688011112042f   // 0.125 * log2(e)

__global__ __launch_bounds__(512) void qkv_gemm_mma(
    const float* __restrict__ bq, const float* __restrict__ bk, const float* __restrict__ bv)
{
    extern __shared__ __align__(1024) char smem[];
    const uint32_t sb = smem_u32(smem);

    const int tid = threadIdx.x;
    const int wid = tid >> 5, lane = tid & 31;
    const int wm = wid & 3, wn = wid >> 2;          // warp tile: 64 x 32
    const int z  = blockIdx.z;
    const int m0 = blockIdx.y * 256;
    const int n0 = blockIdx.x * 128;

    const __nv_bfloat16* Wh = g_Wh + (size_t)z * (D_*D_);
    const __nv_bfloat16* Wl = g_Wl + (size_t)z * (D_*D_);
    const float* bias = (z == 0) ? bq : (z == 1 ? bk : bv);
    __nv_bfloat16* Yh = (z == 0) ? g_Qh : (z == 1 ? g_Kh : g_Vh);
    __nv_bfloat16* Yl = (z == 0) ? g_Ql : (z == 1 ? g_Kl : g_Vl);

    float c[4][4][4];
    #pragma unroll
    for (int mi = 0; mi < 4; mi++)
        #pragma unroll
        for (int nf = 0; nf < 4; nf++)
            #pragma unroll
            for (int r = 0; r < 4; r++) c[mi][nf][r] = 0.f;

    uint32_t rowbyteA[4];
    const int rA = lane & 15;
    const uint32_t kbA = (uint32_t)((lane >> 4) * 16);
    #pragma unroll
    for (int mi = 0; mi < 4; mi++)
        rowbyteA[mi] = (uint32_t)((wm*64 + mi*16 + rA) * 128);
    uint32_t rowbyteB4[2];
    #pragma unroll
    for (int pr = 0; pr < 2; pr++)
        rowbyteB4[pr] = (uint32_t)((wn*32 + pr*16 + (lane & 7) + ((lane >> 4) & 1) * 8) * 128);
    const uint32_t kbB = (uint32_t)(((lane >> 3) & 1) * 16);

    auto load_chunk = [&](int c0, int st) {
        const int k0 = c0 * 64;
        const uint32_t so = sb + (uint32_t)st * G_STAGE;
        #pragma unroll
        for (int it = 0; it < 12; it++) {
            int u = tid + it * 512;
            const __nv_bfloat16* src;
            uint32_t toff;
            int row, seg;
            if (u < 4096) {                     // A: 256 rows, hi then lo
                int v = u & 2047;
                row = v >> 3; seg = v & 7;
                src = (u < 2048 ? g_Xh : g_Xl) + (size_t)(m0 + row) * D_ + k0 + seg*8;
                toff = (u < 2048) ? T_AH : T_AL;
            } else {                            // B: 128 rows, hi then lo
                int u2 = u - 4096;
                int v = u2 & 1023;
                row = v >> 3; seg = v & 7;
                src = (u2 < 1024 ? Wh : Wl) + (size_t)(n0 + row) * D_ + k0 + seg*8;
                toff = (u2 < 1024) ? T_BH : T_BL;
            }
            uint32_t bo = (uint32_t)(row * 128 + seg * 16);
            CP_ASYNC16(so + toff + swz(bo), src);
        }
        CP_COMMIT();
    };

    load_chunk(0, 0);
    for (int c0 = 0; c0 < 16; c0++) {
        CP_WAIT0();
        __syncthreads();
        if (c0 < 15) load_chunk(c0 + 1, (c0 + 1) & 1);

        const uint32_t so = sb + (uint32_t)(c0 & 1) * G_STAGE;
        #pragma unroll
        for (int s = 0; s < 4; s++) {
            const uint32_t kb = (uint32_t)(s * 32);
            uint32_t ah[4][4], al[4][4], bh4[2][4], bl4[2][4];
            #pragma unroll
            for (int mi = 0; mi < 4; mi++) {
                uint32_t bo = rowbyteA[mi] + kb + kbA;
                ldsm_x4(ah[mi], so + T_AH + swz(bo));
                ldsm_x4(al[mi], so + T_AL + swz(bo));
            }
            #pragma unroll
            for (int pr = 0; pr < 2; pr++) {
                uint32_t bo = rowbyteB4[pr] + kb + kbB;
                ldsm_x4(bh4[pr], so + T_BH + swz(bo));
                ldsm_x4(bl4[pr], so + T_BL + swz(bo));
            }
            #pragma unroll
            for (int mi = 0; mi < 4; mi++)
                #pragma unroll
                for (int nf = 0; nf < 4; nf++) {
                    const uint32_t* bh = &bh4[nf >> 1][(nf & 1) * 2];
                    const uint32_t* bl = &bl4[nf >> 1][(nf & 1) * 2];
                    mma_bf16(c[mi][nf], ah[mi], bh);
                    mma_bf16(c[mi][nf], ah[mi], bl);
                    mma_bf16(c[mi][nf], al[mi], bh);
                }
        }
    }

    const int g = lane >> 2, tig = lane & 3;
    const float scl = (z == 0) ? SCL_F : 1.0f;
    #pragma unroll
    for (int mi = 0; mi < 4; mi++) {
        #pragma unroll
        for (int half = 0; half < 2; half++) {
            const int m = m0 + wm*64 + mi*16 + g + half*8;
            const int bb = m >> 10, l = m & 1023;
            #pragma unroll
            for (int nf = 0; nf < 4; nf++) {
                const int n = n0 + wn*32 + nf*8 + 2*tig;
                const int h = n >> 6, dh = n & 63;
                float2 bv2 = *(const float2*)&bias[n];
                float vx = (c[mi][nf][half*2+0] + bv2.x) * scl;
                float vy = (c[mi][nf][half*2+1] + bv2.y) * scl;
                uint32_t hb = pk2bf(vx, vy);
                float hx = __uint_as_float(hb << 16);
                float hy = __uint_as_float(hb & 0xFFFF0000u);
                uint32_t lb = pk2bf(vx - hx, vy - hy);
                size_t idx = (((size_t)(bb*H_ + h))*L_ + l)*DH_ + dh;
                *(uint32_t*)&Yh[idx] = hb;
                *(uint32_t*)&Yl[idx] = lb;
            }
        }
    }
}

// ---------------------------------------------------------------------------
// Flash attention via mma.sync bf16-split, causal, no-max softmax.
// CTA = 128 q rows (8 warps x m16), key tiles of 64, 2-stage cp.async K/V.
// Q tile lives in SMEM (re-read via ldmatrix) -> regs fit 128 -> 2 CTAs/SM.
// ---------------------------------------------------------------------------
#define AT_STAGE 32768          // Kh(8K) Kl(8K) Vh(8K) Vl(8K)
#define AT_QH    65536          // Qh 16K
#define AT_QL    81920          // Ql 16K
#define AT_SMEM  98304

__global__ __launch_bounds__(256, 2) void attn_mma(float* __restrict__ out)
{
    extern __shared__ __align__(1024) char asmem[];
    const uint32_t sb = smem_u32(asmem);
    const int tid = threadIdx.x;
    const int w = tid >> 5, lane = tid & 31;
    const int iq = (int)gridDim.x - 1 - (int)blockIdx.x;   // long CTAs first
    const int bh = blockIdx.y;
    const int b_ = bh >> 4, h = bh & 15;
    const size_t kvbase = (size_t)bh * L_ * DH_;

    const int r0 = lane >> 2;
    const int qc = 2 * (lane & 3);
    const int qrow = iq*128 + w*16;

    // ---- loader: one 64-key tile (Kh,Kl,Vh,Vl) into stage st ----
    auto load_tile = [&](int jt, int st) {
        const uint32_t so = sb + (uint32_t)st * AT_STAGE;
        #pragma unroll
        for (int it = 0; it < 8; it++) {
            int u = tid + it * 256;
            int arr = u >> 9;            // 0 Kh, 1 Kl, 2 Vh, 3 Vl
            int v = u & 511;
            int row = v >> 3, seg = v & 7;
            const __nv_bfloat16* src =
                (arr == 0 ? g_Kh : arr == 1 ? g_Kl : arr == 2 ? g_Vh : g_Vl)
                + kvbase + (size_t)(jt*64 + row)*DH_ + seg*8;
            CP_ASYNC16(so + (uint32_t)arr*8192u + swz((uint32_t)(row*128 + seg*16)), src);
        }
        CP_COMMIT();
    };

    const int jtmax = 2*iq + 1;
    load_tile(0, 0);

    // ---- copy Q tile (128 rows x 64 cols, hi+lo) into smem, swizzled ----
    {
        const size_t qgbase = kvbase + (size_t)(iq*128) * DH_;
        #pragma unroll
        for (int it = 0; it < 4; it++) {
            int u = tid + it * 256;      // 1024 16B-chunks per array
            int row = u >> 3, seg = u & 7;
            uint32_t bo = swz((uint32_t)(row*128 + seg*16));
            *(uint4*)(asmem + AT_QH + bo) =
                *(const uint4*)&g_Qh[qgbase + (size_t)row*DH_ + seg*8];
            *(uint4*)(asmem + AT_QL + bo) =
                *(const uint4*)&g_Ql[qgbase + (size_t)row*DH_ + seg*8];
        }
    }

    float co[8][4];
    #pragma unroll
    for (int j = 0; j < 8; j++)
        #pragma unroll
        for (int r = 0; r < 4; r++) co[j][r] = 0.f;
    float lp0 = 0.f, lp1 = 0.f;

    // Q A-operand ldmatrix base; K x4 base; V-trans x4 base
    const uint32_t rowbyteQ = (uint32_t)((w*16 + (lane & 15)) * 128);
    const uint32_t kbQ   = (uint32_t)((lane >> 4) * 16);
    const uint32_t kRowB = (uint32_t)((lane & 7) + ((lane >> 4) & 1) * 8);
    const uint32_t kbB   = (uint32_t)(((lane >> 3) & 1) * 16);
    const uint32_t vRowB = (uint32_t)(((lane >> 3) & 1) * 8 + (lane & 7));
    const uint32_t vColB = (uint32_t)(((lane >> 4) & 1) * 16);

    for (int jt = 0; jt <= jtmax; jt++) {
        CP_WAIT0();
        __syncthreads();                     // KV ready; also orders Q stores (jt=0)
        if (jt < jtmax) load_tile(jt + 1, (jt + 1) & 1);

        const uint32_t sK_h = sb + (uint32_t)(jt & 1) * AT_STAGE;
        const uint32_t sK_l = sK_h + 8192u;
        const uint32_t sV_h = sK_h + 16384u;
        const uint32_t sV_l = sK_h + 24576u;

        // ---- S = Q K^T (3-term split), fp32 acc; Q frags from smem ----
        float cs[8][4];
        #pragma unroll
        for (int j = 0; j < 8; j++)
            #pragma unroll
            for (int r = 0; r < 4; r++) cs[j][r] = 0.f;

        #pragma unroll
        for (int s = 0; s < 4; s++) {
            uint32_t qbo = rowbyteQ + (uint32_t)(s * 32) + kbQ;
            uint32_t qh4[4], ql4[4];
            ldsm_x4(qh4, sb + AT_QH + swz(qbo));
            ldsm_x4(ql4, sb + AT_QL + swz(qbo));
            const uint32_t kb = (uint32_t)(s * 32) + kbB;
            #pragma unroll
            for (int p = 0; p < 4; p++) {
                uint32_t bo = (uint32_t)(p * 16 * 128) + kRowB * 128 + kb;
                uint32_t kh4[4], kl4[4];
                ldsm_x4(kh4, sK_h + swz(bo));
                ldsm_x4(kl4, sK_l + swz(bo));
                mma_bf16(cs[2*p],   qh4, &kh4[0]);
                mma_bf16(cs[2*p],   qh4, &kl4[0]);
                mma_bf16(cs[2*p],   ql4, &kh4[0]);
                mma_bf16(cs[2*p+1], qh4, &kh4[2]);
                mma_bf16(cs[2*p+1], qh4, &kl4[2]);
                mma_bf16(cs[2*p+1], ql4, &kh4[2]);
            }
        }

        // ---- softmax (no running max; S already includes 1/8*log2e) ----
        uint32_t uh0[8], uh1[8], ul0[8], ul1[8];
        const bool diag = (jt >= 2*iq);
        const int rg0 = qrow + r0;
        #pragma unroll
        for (int j = 0; j < 8; j++) {
            float p0 = ex2(cs[j][0]);
            float p1 = ex2(cs[j][1]);
            float p2 = ex2(cs[j][2]);
            float p3 = ex2(cs[j][3]);
            if (diag) {
                int c0 = jt*64 + j*8 + qc;
                if (c0     > rg0)     p0 = 0.f;
                if (c0 + 1 > rg0)     p1 = 0.f;
                if (c0     > rg0 + 8) p2 = 0.f;
                if (c0 + 1 > rg0 + 8) p3 = 0.f;
            }
            lp0 += p0 + p1;
            lp1 += p2 + p3;
            uint32_t h0 = pk2bf(p0, p1);
            uint32_t h1 = pk2bf(p2, p3);
            uh0[j] = h0; uh1[j] = h1;
            float h0x = __uint_as_float(h0 << 16), h0y = __uint_as_float(h0 & 0xFFFF0000u);
            float h1x = __uint_as_float(h1 << 16), h1y = __uint_as_float(h1 & 0xFFFF0000u);
            ul0[j] = pk2bf(p0 - h0x, p1 - h0y);
            ul1[j] = pk2bf(p2 - h1x, p3 - h1y);
        }

        // ---- O += P V (3-term split), V via ldmatrix.trans x4 ----
        #pragma unroll
        for (int t = 0; t < 4; t++) {
            uint32_t Ah[4] = { uh0[2*t], uh1[2*t], uh0[2*t+1], uh1[2*t+1] };
            uint32_t Al[4] = { ul0[2*t], ul1[2*t], ul0[2*t+1], ul1[2*t+1] };
            const uint32_t vrow = (uint32_t)((t*16 + vRowB) * 128);
            #pragma unroll
            for (int p = 0; p < 4; p++) {
                uint32_t bo = vrow + (uint32_t)(p * 32) + vColB;
                uint32_t vh4[4], vl4[4];
                ldsm_x4_t(vh4, sV_h + swz(bo));
                ldsm_x4_t(vl4, sV_l + swz(bo));
                mma_bf16(co[2*p],   Ah, &vh4[0]);
                mma_bf16(co[2*p],   Ah, &vl4[0]);
                mma_bf16(co[2*p],   Al, &vh4[0]);
                mma_bf16(co[2*p+1], Ah, &vh4[2]);
                mma_bf16(co[2*p+1], Ah, &vl4[2]);
                mma_bf16(co[2*p+1], Al, &vh4[2]);
            }
        }
    }

    // ---- row-sum reduce over quad (cols live in lane&3) ----
    lp0 += __shfl_xor_sync(0xffffffffu, lp0, 1);
    lp0 += __shfl_xor_sync(0xffffffffu, lp0, 2);
    lp1 += __shfl_xor_sync(0xffffffffu, lp1, 1);
    lp1 += __shfl_xor_sync(0xffffffffu, lp1, 2);
    const float inv0 = 1.f / lp0;
    const float inv1 = 1.f / lp1;

    const int l0 = qrow + r0;
    #pragma unroll
    for (int jn = 0; jn < 8; jn++) {
        const int d = h*DH_ + jn*8 + qc;
        float2 r0v; r0v.x = co[jn][0] * inv0; r0v.y = co[jn][1] * inv0;
        float2 r1v; r1v.x = co[jn][2] * inv1; r1v.y = co[jn][3] * inv1;
        *(float2*)&out[((size_t)(b_*L_ + l0    ))*D_ + d] = r0v;
        *(float2*)&out[((size_t)(b_*L_ + l0 + 8))*D_ + d] = r1v;
    }
}

// ---------------------------------------------------------------------------
extern "C" void kernel_launch(void* const* d_in, const int* in_sizes, int n_in,
                              void* d_out, int out_size)
{
    const float* seq = (const float*)d_in[0];
    const float* Wq = (const float*)d_in[3];
    const float* bq = (const float*)d_in[4];
    const float* Wk = (const float*)d_in[5];
    const float* bk = (const float*)d_in[6];
    const float* Wv = (const float*)d_in[7];
    const float* bv = (const float*)d_in[8];
    float* out = (float*)d_out;

    const int total4 = NX4 + 3 * NW4;
    cvt_all<<<(total4 + 255)/256, 256>>>((const float4*)seq, (const float4*)Wq,
                                         (const float4*)Wk, (const float4*)Wv);

    cudaFuncSetAttribute(qkv_gemm_mma, cudaFuncAttributeMaxDynamicSharedMemorySize, GSMEM);
    qkv_gemm_mma<<<dim3(D_/128, M_/256, 3), 512, GSMEM>>>(bq, bk, bv);

    cudaFuncSetAttribute(attn_mma, cudaFuncAttributeMaxDynamicSharedMemorySize, AT_SMEM);
    attn_mma<<<dim3(L_/128, B_*H_), 256, AT_SMEM>>>(out);
}

// round 15
// speedup vs baseline: 1.0278x; 1.0278x over previous
#include <cuda_runtime.h>
#include <cuda_bf16.h>
#include <math.h>
#include <stdint.h>

#define B_ 4
#define L_ 1024
#define D_ 1024
#define H_ 16
#define DH_ 64
#define M_ (B_*L_)

// ---------------- scratch ----------------
__device__ __nv_bfloat16 g_Xh[M_*D_];
__device__ __nv_bfloat16 g_Xl[M_*D_];
__device__ __nv_bfloat16 g_Wh[3*D_*D_];
__device__ __nv_bfloat16 g_Wl[3*D_*D_];
// Q/K/V bf16 hi/lo splits in [b][h][l][dh] layout (Q pre-scaled by SCL)
__device__ __nv_bfloat16 g_Qh[B_*H_*L_*DH_];
__device__ __nv_bfloat16 g_Ql[B_*H_*L_*DH_];
__device__ __nv_bfloat16 g_Kh[B_*H_*L_*DH_];
__device__ __nv_bfloat16 g_Kl[B_*H_*L_*DH_];
__device__ __nv_bfloat16 g_Vh[B_*H_*L_*DH_];
__device__ __nv_bfloat16 g_Vl[B_*H_*L_*DH_];

// ---------------- helpers ----------------
__device__ __forceinline__ uint32_t smem_u32(const void* p) {
    uint32_t a;
    asm("{ .reg .u64 t; cvta.to.shared.u64 t, %1; cvt.u32.u64 %0, t; }" : "=r"(a) : "l"(p));
    return a;
}
__device__ __forceinline__ float ex2(float x) {
    float y; asm("ex2.approx.ftz.f32 %0, %1;" : "=f"(y) : "f"(x)); return y;
}
__device__ __forceinline__ uint32_t pk2bf(float lo, float hi) {
    uint32_t r;
    asm("cvt.rn.bf16x2.f32 %0, %1, %2;" : "=r"(r) : "f"(hi), "f"(lo));
    return r;
}

#define CP_ASYNC16(dst, src) \
    asm volatile("cp.async.cg.shared.global [%0], [%1], 16;" :: "r"(dst), "l"(src) : "memory")
#define CP_COMMIT() asm volatile("cp.async.commit_group;" ::: "memory")
#define CP_WAIT0()  asm volatile("cp.async.wait_group 0;" ::: "memory")
#define CP_WAIT1()  asm volatile("cp.async.wait_group 1;" ::: "memory")

__device__ __forceinline__ void ldsm_x4(uint32_t* r, uint32_t addr) {
    asm volatile("ldmatrix.sync.aligned.m8n8.x4.shared.b16 {%0,%1,%2,%3}, [%4];"
        : "=r"(r[0]), "=r"(r[1]), "=r"(r[2]), "=r"(r[3]) : "r"(addr));
}
__device__ __forceinline__ void ldsm_x4_t(uint32_t* r, uint32_t addr) {
    asm volatile("ldmatrix.sync.aligned.m8n8.x4.trans.shared.b16 {%0,%1,%2,%3}, [%4];"
        : "=r"(r[0]), "=r"(r[1]), "=r"(r[2]), "=r"(r[3]) : "r"(addr));
}
__device__ __forceinline__ void mma_bf16(float* c, const uint32_t* a, const uint32_t* b) {
    asm volatile("mma.sync.aligned.m16n8k16.row.col.f32.bf16.bf16.f32 "
        "{%0,%1,%2,%3}, {%4,%5,%6,%7}, {%8,%9}, {%0,%1,%2,%3};"
        : "+f"(c[0]), "+f"(c[1]), "+f"(c[2]), "+f"(c[3])
        : "r"(a[0]), "r"(a[1]), "r"(a[2]), "r"(a[3]), "r"(b[0]), "r"(b[1]));
}
__device__ __forceinline__ uint32_t swz(uint32_t bo) { return bo ^ ((bo >> 3) & 0x70); }

// ---------------------------------------------------------------------------
// Merged split fp32 -> bf16 (hi, lo) for X, Wq, Wk, Wv in ONE launch.
// ---------------------------------------------------------------------------
#define NX4 (M_*D_/4)
#define NW4 (D_*D_/4)

__global__ __launch_bounds__(256) void cvt_all(
    const float4* __restrict__ X,  const float4* __restrict__ Wq,
    const float4* __restrict__ Wk, const float4* __restrict__ Wv)
{
    int i = blockIdx.x * 256 + threadIdx.x;
    const float4* src; __nv_bfloat16* dh; __nv_bfloat16* dl; int off;
    if (i < NX4) { src = X; off = i; dh = g_Xh; dl = g_Xl; }
    else {
        int wI = i - NX4;
        int s  = wI / NW4;          // 0,1,2
        off = wI - s * NW4;
        src = (s == 0) ? Wq : (s == 1 ? Wk : Wv);
        dh = g_Wh + (size_t)s * (D_*D_);
        dl = g_Wl + (size_t)s * (D_*D_);
    }
    float4 v = src[off];
    float f[4] = {v.x, v.y, v.z, v.w};
    union { __nv_bfloat16 b[4]; uint2 u; } Hh, Ll;
    #pragma unroll
    for (int j = 0; j < 4; j++) {
        __nv_bfloat16 hb = __float2bfloat16(f[j]);
        Hh.b[j] = hb;
        Ll.b[j] = __float2bfloat16(f[j] - __bfloat162float(hb));
    }
    *(uint2*)(dh + (size_t)off * 4) = Hh.u;
    *(uint2*)(dl + (size_t)off * 4) = Ll.u;
}

// ---------------------------------------------------------------------------
// QKV GEMM via mma.sync bf16 (3-term): CTA 256x128, BK=64, 16 warps (4x4),
// 2-stage single-sync cp.async pipeline. (unchanged from R12)
// ---------------------------------------------------------------------------
#define T_AH 0
#define T_AL 32768
#define T_BH 65536
#define T_BL 81920
#define G_STAGE 98304
#define GSMEM (2*G_STAGE)
#define SCL_F 0.18033688011112042f   // 0.125 * log2(e)

__global__ __launch_bounds__(512) void qkv_gemm_mma(
    const float* __restrict__ bq, const float* __restrict__ bk, const float* __restrict__ bv)
{
    extern __shared__ __align__(1024) char smem[];
    const uint32_t sb = smem_u32(smem);

    const int tid = threadIdx.x;
    const int wid = tid >> 5, lane = tid & 31;
    const int wm = wid & 3, wn = wid >> 2;          // warp tile: 64 x 32
    const int z  = blockIdx.z;
    const int m0 = blockIdx.y * 256;
    const int n0 = blockIdx.x * 128;

    const __nv_bfloat16* Wh = g_Wh + (size_t)z * (D_*D_);
    const __nv_bfloat16* Wl = g_Wl + (size_t)z * (D_*D_);
    const float* bias = (z == 0) ? bq : (z == 1 ? bk : bv);
    __nv_bfloat16* Yh = (z == 0) ? g_Qh : (z == 1 ? g_Kh : g_Vh);
    __nv_bfloat16* Yl = (z == 0) ? g_Ql : (z == 1 ? g_Kl : g_Vl);

    float c[4][4][4];
    #pragma unroll
    for (int mi = 0; mi < 4; mi++)
        #pragma unroll
        for (int nf = 0; nf < 4; nf++)
            #pragma unroll
            for (int r = 0; r < 4; r++) c[mi][nf][r] = 0.f;

    uint32_t rowbyteA[4];
    const int rA = lane & 15;
    const uint32_t kbA = (uint32_t)((lane >> 4) * 16);
    #pragma unroll
    for (int mi = 0; mi < 4; mi++)
        rowbyteA[mi] = (uint32_t)((wm*64 + mi*16 + rA) * 128);
    uint32_t rowbyteB4[2];
    #pragma unroll
    for (int pr = 0; pr < 2; pr++)
        rowbyteB4[pr] = (uint32_t)((wn*32 + pr*16 + (lane & 7) + ((lane >> 4) & 1) * 8) * 128);
    const uint32_t kbB = (uint32_t)(((lane >> 3) & 1) * 16);

    auto load_chunk = [&](int c0, int st) {
        const int k0 = c0 * 64;
        const uint32_t so = sb + (uint32_t)st * G_STAGE;
        #pragma unroll
        for (int it = 0; it < 12; it++) {
            int u = tid + it * 512;
            const __nv_bfloat16* src;
            uint32_t toff;
            int row, seg;
            if (u < 4096) {                     // A: 256 rows, hi then lo
                int v = u & 2047;
                row = v >> 3; seg = v & 7;
                src = (u < 2048 ? g_Xh : g_Xl) + (size_t)(m0 + row) * D_ + k0 + seg*8;
                toff = (u < 2048) ? T_AH : T_AL;
            } else {                            // B: 128 rows, hi then lo
                int u2 = u - 4096;
                int v = u2 & 1023;
                row = v >> 3; seg = v & 7;
                src = (u2 < 1024 ? Wh : Wl) + (size_t)(n0 + row) * D_ + k0 + seg*8;
                toff = (u2 < 1024) ? T_BH : T_BL;
            }
            uint32_t bo = (uint32_t)(row * 128 + seg * 16);
            CP_ASYNC16(so + toff + swz(bo), src);
        }
        CP_COMMIT();
    };

    load_chunk(0, 0);
    for (int c0 = 0; c0 < 16; c0++) {
        CP_WAIT0();
        __syncthreads();
        if (c0 < 15) load_chunk(c0 + 1, (c0 + 1) & 1);

        const uint32_t so = sb + (uint32_t)(c0 & 1) * G_STAGE;
        #pragma unroll
        for (int s = 0; s < 4; s++) {
            const uint32_t kb = (uint32_t)(s * 32);
            uint32_t ah[4][4], al[4][4], bh4[2][4], bl4[2][4];
            #pragma unroll
            for (int mi = 0; mi < 4; mi++) {
                uint32_t bo = rowbyteA[mi] + kb + kbA;
                ldsm_x4(ah[mi], so + T_AH + swz(bo));
                ldsm_x4(al[mi], so + T_AL + swz(bo));
            }
            #pragma unroll
            for (int pr = 0; pr < 2; pr++) {
                uint32_t bo = rowbyteB4[pr] + kb + kbB;
                ldsm_x4(bh4[pr], so + T_BH + swz(bo));
                ldsm_x4(bl4[pr], so + T_BL + swz(bo));
            }
            #pragma unroll
            for (int mi = 0; mi < 4; mi++)
                #pragma unroll
                for (int nf = 0; nf < 4; nf++) {
                    const uint32_t* bh = &bh4[nf >> 1][(nf & 1) * 2];
                    const uint32_t* bl = &bl4[nf >> 1][(nf & 1) * 2];
                    mma_bf16(c[mi][nf], ah[mi], bh);
                    mma_bf16(c[mi][nf], ah[mi], bl);
                    mma_bf16(c[mi][nf], al[mi], bh);
                }
        }
    }

    const int g = lane >> 2, tig = lane & 3;
    const float scl = (z == 0) ? SCL_F : 1.0f;
    #pragma unroll
    for (int mi = 0; mi < 4; mi++) {
        #pragma unroll
        for (int half = 0; half < 2; half++) {
            const int m = m0 + wm*64 + mi*16 + g + half*8;
            const int bb = m >> 10, l = m & 1023;
            #pragma unroll
            for (int nf = 0; nf < 4; nf++) {
                const int n = n0 + wn*32 + nf*8 + 2*tig;
                const int h = n >> 6, dh = n & 63;
                float2 bv2 = *(const float2*)&bias[n];
                float vx = (c[mi][nf][half*2+0] + bv2.x) * scl;
                float vy = (c[mi][nf][half*2+1] + bv2.y) * scl;
                uint32_t hb = pk2bf(vx, vy);
                float hx = __uint_as_float(hb << 16);
                float hy = __uint_as_float(hb & 0xFFFF0000u);
                uint32_t lb = pk2bf(vx - hx, vy - hy);
                size_t idx = (((size_t)(bb*H_ + h))*L_ + l)*DH_ + dh;
                *(uint32_t*)&Yh[idx] = hb;
                *(uint32_t*)&Yl[idx] = lb;
            }
        }
    }
}

// ---------------------------------------------------------------------------
// Flash attention via mma.sync bf16-split, causal, no-max softmax.
// CTA = 128 q rows (8 warps x m16), key tiles of 64, 3-stage single-sync
// cp.async K/V pipeline. Warps 0-3 skip the fully-masked final tile.
// ---------------------------------------------------------------------------
#define AT_STAGE 32768          // Kh(8K) Kl(8K) Vh(8K) Vl(8K)
#define AT_SMEM  (3*AT_STAGE)

__global__ __launch_bounds__(256) void attn_mma(float* __restrict__ out)
{
    extern __shared__ __align__(1024) char asmem[];
    const uint32_t sb = smem_u32(asmem);
    const int tid = threadIdx.x;
    const int w = tid >> 5, lane = tid & 31;
    const int iq = (int)gridDim.x - 1 - (int)blockIdx.x;   // long CTAs first
    const int bh = blockIdx.y;
    const int b_ = bh >> 4, h = bh & 15;
    const size_t kvbase = (size_t)bh * L_ * DH_;

    // ---- Q fragments (A operand), loaded once from gmem ----
    const int r0 = lane >> 2;
    const int qc = 2 * (lane & 3);
    const int qrow = iq*128 + w*16;
    uint32_t qh[4][4], ql[4][4];
    #pragma unroll
    for (int s = 0; s < 4; s++)
        #pragma unroll
        for (int i = 0; i < 4; i++) {
            int rr = qrow + r0 + (i & 1) * 8;
            int cc = s*16 + qc + (i >> 1) * 8;
            qh[s][i] = *(const uint32_t*)&g_Qh[kvbase + (size_t)rr*DH_ + cc];
            ql[s][i] = *(const uint32_t*)&g_Ql[kvbase + (size_t)rr*DH_ + cc];
        }

    float co[8][4];
    #pragma unroll
    for (int j = 0; j < 8; j++)
        #pragma unroll
        for (int r = 0; r < 4; r++) co[j][r] = 0.f;
    float lp0 = 0.f, lp1 = 0.f;

    // ---- loader: one 64-key tile (Kh,Kl,Vh,Vl) into stage st ----
    auto load_tile = [&](int jt, int st) {
        const uint32_t so = sb + (uint32_t)st * AT_STAGE;
        #pragma unroll
        for (int it = 0; it < 8; it++) {
            int u = tid + it * 256;
            int arr = u >> 9;            // 0 Kh, 1 Kl, 2 Vh, 3 Vl
            int v = u & 511;
            int row = v >> 3, seg = v & 7;
            const __nv_bfloat16* src =
                (arr == 0 ? g_Kh : arr == 1 ? g_Kl : arr == 2 ? g_Vh : g_Vl)
                + kvbase + (size_t)(jt*64 + row)*DH_ + seg*8;
            CP_ASYNC16(so + (uint32_t)arr*8192u + swz((uint32_t)(row*128 + seg*16)), src);
        }
        CP_COMMIT();
    };

    const int jtmax = 2*iq + 1;
    load_tile(0, 0);
    load_tile(1, 1);          // jtmax >= 1 always

    // K-operand x4 base (two n8 tiles per load), V-trans x4 base
    const uint32_t kRowB = (uint32_t)((lane & 7) + ((lane >> 4) & 1) * 8);
    const uint32_t kbB   = (uint32_t)(((lane >> 3) & 1) * 16);
    const uint32_t vRowB = (uint32_t)(((lane >> 3) & 1) * 8 + (lane & 7));
    const uint32_t vColB = (uint32_t)(((lane >> 4) & 1) * 16);

    int st = 0;               // stage of tile jt
    for (int jt = 0; jt <= jtmax; jt++) {
        if (jt < jtmax) CP_WAIT1(); else CP_WAIT0();
        __syncthreads();
        if (jt + 2 <= jtmax) {
            int st2 = st + 2; if (st2 >= 3) st2 -= 3;
            load_tile(jt + 2, st2);
        }

        const uint32_t sK_h = sb + (uint32_t)st * AT_STAGE;
        const uint32_t sK_l = sK_h + 8192u;
        const uint32_t sV_h = sK_h + 16384u;
        const uint32_t sV_l = sK_h + 24576u;
        if (++st >= 3) st = 0;

        // Final tile is entirely above the causal diagonal for warps 0-3
        // (their max row iq*128+63 < first key (2iq+1)*64): skip all compute.
        if (jt == jtmax && w < 4) continue;

        // ---- S = Q K^T (3-term split), fp32 acc ----
        float cs[8][4];
        #pragma unroll
        for (int j = 0; j < 8; j++)
            #pragma unroll
            for (int r = 0; r < 4; r++) cs[j][r] = 0.f;

        #pragma unroll
        for (int s = 0; s < 4; s++) {
            const uint32_t kb = (uint32_t)(s * 32) + kbB;
            #pragma unroll
            for (int p = 0; p < 4; p++) {
                uint32_t bo = (uint32_t)(p * 16 * 128) + kRowB * 128 + kb;
                uint32_t kh4[4], kl4[4];
                ldsm_x4(kh4, sK_h + swz(bo));
                ldsm_x4(kl4, sK_l + swz(bo));
                mma_bf16(cs[2*p],   qh[s], &kh4[0]);
                mma_bf16(cs[2*p],   qh[s], &kl4[0]);
                mma_bf16(cs[2*p],   ql[s], &kh4[0]);
                mma_bf16(cs[2*p+1], qh[s], &kh4[2]);
                mma_bf16(cs[2*p+1], qh[s], &kl4[2]);
                mma_bf16(cs[2*p+1], ql[s], &kh4[2]);
            }
        }

        // ---- softmax (no running max; S already includes 1/8*log2e) ----
        uint32_t uh0[8], uh1[8], ul0[8], ul1[8];
        const bool diag = (jt >= 2*iq);
        const int rg0 = qrow + r0;
        #pragma unroll
        for (int j = 0; j < 8; j++) {
            float p0 = ex2(cs[j][0]);
            float p1 = ex2(cs[j][1]);
            float p2 = ex2(cs[j][2]);
            float p3 = ex2(cs[j][3]);
            if (diag) {
                int c0 = jt*64 + j*8 + qc;
                if (c0     > rg0)     p0 = 0.f;
                if (c0 + 1 > rg0)     p1 = 0.f;
                if (c0     > rg0 + 8) p2 = 0.f;
                if (c0 + 1 > rg0 + 8) p3 = 0.f;
            }
            lp0 += p0 + p1;
            lp1 += p2 + p3;
            uint32_t h0 = pk2bf(p0, p1);
            uint32_t h1 = pk2bf(p2, p3);
            uh0[j] = h0; uh1[j] = h1;
            float h0x = __uint_as_float(h0 << 16), h0y = __uint_as_float(h0 & 0xFFFF0000u);
            float h1x = __uint_as_float(h1 << 16), h1y = __uint_as_float(h1 & 0xFFFF0000u);
            ul0[j] = pk2bf(p0 - h0x, p1 - h0y);
            ul1[j] = pk2bf(p2 - h1x, p3 - h1y);
        }

        // ---- O += P V (3-term split), V via ldmatrix.trans x4 ----
        #pragma unroll
        for (int t = 0; t < 4; t++) {
            uint32_t Ah[4] = { uh0[2*t], uh1[2*t], uh0[2*t+1], uh1[2*t+1] };
            uint32_t Al[4] = { ul0[2*t], ul1[2*t], ul0[2*t+1], ul1[2*t+1] };
            const uint32_t vrow = (uint32_t)((t*16 + vRowB) * 128);
            #pragma unroll
            for (int p = 0; p < 4; p++) {
                uint32_t bo = vrow + (uint32_t)(p * 32) + vColB;
                uint32_t vh4[4], vl4[4];
                ldsm_x4_t(vh4, sV_h + swz(bo));
                ldsm_x4_t(vl4, sV_l + swz(bo));
                mma_bf16(co[2*p],   Ah, &vh4[0]);
                mma_bf16(co[2*p],   Ah, &vl4[0]);
                mma_bf16(co[2*p],   Al, &vh4[0]);
                mma_bf16(co[2*p+1], Ah, &vh4[2]);
                mma_bf16(co[2*p+1], Ah, &vl4[2]);
                mma_bf16(co[2*p+1], Al, &vh4[2]);
            }
        }
    }

    // ---- row-sum reduce over quad (cols live in lane&3) ----
    lp0 += __shfl_xor_sync(0xffffffffu, lp0, 1);
    lp0 += __shfl_xor_sync(0xffffffffu, lp0, 2);
    lp1 += __shfl_xor_sync(0xffffffffu, lp1, 1);
    lp1 += __shfl_xor_sync(0xffffffffu, lp1, 2);
    const float inv0 = 1.f / lp0;
    const float inv1 = 1.f / lp1;

    const int l0 = qrow + r0;
    #pragma unroll
    for (int jn = 0; jn < 8; jn++) {
        const int d = h*DH_ + jn*8 + qc;
        float2 r0v; r0v.x = co[jn][0] * inv0; r0v.y = co[jn][1] * inv0;
        float2 r1v; r1v.x = co[jn][2] * inv1; r1v.y = co[jn][3] * inv1;
        *(float2*)&out[((size_t)(b_*L_ + l0    ))*D_ + d] = r0v;
        *(float2*)&out[((size_t)(b_*L_ + l0 + 8))*D_ + d] = r1v;
    }
}

// ---------------------------------------------------------------------------
extern "C" void kernel_launch(void* const* d_in, const int* in_sizes, int n_in,
                              void* d_out, int out_size)
{
    const float* seq = (const float*)d_in[0];
    const float* Wq = (const float*)d_in[3];
    const float* bq = (const float*)d_in[4];
    const float* Wk = (const float*)d_in[5];
    const float* bk = (const float*)d_in[6];
    const float* Wv = (const float*)d_in[7];
    const float* bv = (const float*)d_in[8];
    float* out = (float*)d_out;

    const int total4 = NX4 + 3 * NW4;
    cvt_all<<<(total4 + 255)/256, 256>>>((const float4*)seq, (const float4*)Wq,
                                         (const float4*)Wk, (const float4*)Wv);

    cudaFuncSetAttribute(qkv_gemm_mma, cudaFuncAttributeMaxDynamicSharedMemorySize, GSMEM);
    qkv_gemm_mma<<<dim3(D_/128, M_/256, 3), 512, GSMEM>>>(bq, bk, bv);

    cudaFuncSetAttribute(attn_mma, cudaFuncAttributeMaxDynamicSharedMemorySize, AT_SMEM);
    attn_mma<<<dim3(L_/128, B_*H_), 256, AT_SMEM>>>(out);
}